// round 1
// baseline (speedup 1.0000x reference)
#include <cuda_runtime.h>
#include <cstdint>

#define N_NODES 100000
#define MAX_F   200

// Scratch (allocation-free rule: __device__ globals)
__device__ float g_tmp [N_NODES * MAX_F];   // GEMM output of current layer
__device__ float g_bufA[N_NODES * MAX_F];   // layer activations ping
__device__ float g_bufB[N_NODES * MAX_F];   // layer activations pong
__device__ float g_dinv[N_NODES];
__device__ int   g_deg [N_NODES];

// ---------------------------------------------------------------------------
// degree / normalization
// ---------------------------------------------------------------------------
__global__ void deg_init_kernel(int* deg, int n) {
    int i = blockIdx.x * blockDim.x + threadIdx.x;
    if (i < n) deg[i] = 1;  // self loop
}

__global__ void deg_count_kernel(const int* __restrict__ dst, int* deg, int E) {
    int e = blockIdx.x * blockDim.x + threadIdx.x;
    if (e < E) atomicAdd(&deg[dst[e]], 1);
}

__global__ void dinv_kernel(const int* __restrict__ deg, float* dinv, int n) {
    int i = blockIdx.x * blockDim.x + threadIdx.x;
    if (i < n) dinv[i] = rsqrtf((float)deg[i]);
}

// ---------------------------------------------------------------------------
// GEMM: C[M,N] = (relu?)A[M,K] @ W[K,N]   (fp32, 64x64x16 tiles, 4x4/thread)
// ---------------------------------------------------------------------------
__global__ void gemm_kernel(const float* __restrict__ A,
                            const float* __restrict__ W,
                            float* __restrict__ C,
                            int M, int K, int N, int doRelu) {
    __shared__ float As[16][65];
    __shared__ float Bs[16][64];

    const int bm = blockIdx.y, bn = blockIdx.x;
    const int tid = threadIdx.y * 16 + threadIdx.x;
    const int row0 = bm * 64, col0 = bn * 64;

    float acc[4][4];
#pragma unroll
    for (int i = 0; i < 4; i++)
#pragma unroll
        for (int j = 0; j < 4; j++) acc[i][j] = 0.0f;

    for (int k0 = 0; k0 < K; k0 += 16) {
        // load 64x16 A tile
        const int am = tid >> 2;          // 0..63
        const int ak = (tid & 3) * 4;     // 0,4,8,12
        const int grow = row0 + am;
#pragma unroll
        for (int i = 0; i < 4; i++) {
            const int gk = k0 + ak + i;
            float v = 0.0f;
            if (grow < M && gk < K) v = A[(long)grow * K + gk];
            if (doRelu) v = fmaxf(v, 0.0f);
            As[ak + i][am] = v;
        }
        // load 16x64 W tile
        const int wk = tid >> 4;          // 0..15
        const int wn = (tid & 15) * 4;
#pragma unroll
        for (int i = 0; i < 4; i++) {
            const int gn = col0 + wn + i;
            const int gk = k0 + wk;
            float v = 0.0f;
            if (gk < K && gn < N) v = W[(long)gk * N + gn];
            Bs[wk][wn + i] = v;
        }
        __syncthreads();

#pragma unroll
        for (int kk = 0; kk < 16; kk++) {
            float a[4], b[4];
#pragma unroll
            for (int i = 0; i < 4; i++) a[i] = As[kk][threadIdx.y * 4 + i];
#pragma unroll
            for (int j = 0; j < 4; j++) b[j] = Bs[kk][threadIdx.x * 4 + j];
#pragma unroll
            for (int i = 0; i < 4; i++)
#pragma unroll
                for (int j = 0; j < 4; j++)
                    acc[i][j] = fmaf(a[i], b[j], acc[i][j]);
        }
        __syncthreads();
    }

#pragma unroll
    for (int i = 0; i < 4; i++) {
        const int r = row0 + threadIdx.y * 4 + i;
        if (r >= M) continue;
#pragma unroll
        for (int j = 0; j < 4; j++) {
            const int c = col0 + threadIdx.x * 4 + j;
            if (c < N) C[(long)r * N + c] = acc[i][j];
        }
    }
}

// ---------------------------------------------------------------------------
// agg init: self-loop contribution + bias
//   agg[i][f] = tmp[i][f] * dinv[i]^2 + b[f]
// ---------------------------------------------------------------------------
__global__ void init_agg_kernel(const float* __restrict__ tmp,
                                const float* __restrict__ b,
                                const float* __restrict__ dinv,
                                float* __restrict__ agg,
                                int n, int F) {
    long idx = (long)blockIdx.x * blockDim.x + threadIdx.x;
    const long total = (long)n * F;
    if (idx >= total) return;
    const int i = (int)(idx / F);
    const int f = (int)(idx - (long)i * F);
    const float d = dinv[i];
    agg[idx] = tmp[idx] * d * d + b[f];
}

// ---------------------------------------------------------------------------
// edge scatter: one warp per edge, atomicAdd into agg[dst]
// ---------------------------------------------------------------------------
__global__ void scatter_kernel(const float* __restrict__ tmp,
                               const int* __restrict__ src,
                               const int* __restrict__ dst,
                               const float* __restrict__ dinv,
                               float* __restrict__ agg,
                               int E, int F) {
    const int gtid = blockIdx.x * blockDim.x + threadIdx.x;
    const int e = gtid >> 5;
    const int lane = gtid & 31;
    if (e >= E) return;
    const int s = src[e];
    const int d = dst[e];
    const float w = dinv[s] * dinv[d];
    const float* trow = tmp + (long)s * F;
    float* arow = agg + (long)d * F;
    for (int f = lane; f < F; f += 32) {
        atomicAdd(&arow[f], trow[f] * w);
    }
}

// ---------------------------------------------------------------------------
// host
// ---------------------------------------------------------------------------
extern "C" void kernel_launch(void* const* d_in, const int* in_sizes, int n_in,
                              void* d_out, int out_size) {
    const float* x   = (const float*)d_in[0];
    const int* eidx  = (const int*)d_in[1];
    const int E      = in_sizes[1] / 2;
    const int* src   = eidx;
    const int* dstp  = eidx + E;

    const float* W[5] = { (const float*)d_in[2], (const float*)d_in[4],
                          (const float*)d_in[6], (const float*)d_in[8],
                          (const float*)d_in[10] };
    const float* B[5] = { (const float*)d_in[3], (const float*)d_in[5],
                          (const float*)d_in[7], (const float*)d_in[9],
                          (const float*)d_in[11] };
    const int dims[6] = {512, 200, 175, 125, 75, 50};
    const int N = N_NODES;

    float *tmp, *bufA, *bufB, *dinv;
    int* deg;
    cudaGetSymbolAddress((void**)&tmp,  g_tmp);
    cudaGetSymbolAddress((void**)&bufA, g_bufA);
    cudaGetSymbolAddress((void**)&bufB, g_bufB);
    cudaGetSymbolAddress((void**)&dinv, g_dinv);
    cudaGetSymbolAddress((void**)&deg,  g_deg);

    // degrees + normalization
    deg_init_kernel<<<(N + 255) / 256, 256>>>(deg, N);
    deg_count_kernel<<<(E + 255) / 256, 256>>>(dstp, deg, E);
    dinv_kernel<<<(N + 255) / 256, 256>>>(deg, dinv, N);

    const float* in_act = x;
    float* outs[5] = { bufA, bufB, bufA, bufB, (float*)d_out };

    for (int L = 0; L < 5; L++) {
        const int Fin = dims[L], Fout = dims[L + 1];
        float* agg = outs[L];

        dim3 ggrid((Fout + 63) / 64, (N + 63) / 64);
        dim3 gblk(16, 16);
        gemm_kernel<<<ggrid, gblk>>>(in_act, W[L], tmp, N, Fin, Fout, L > 0 ? 1 : 0);

        const long total = (long)N * Fout;
        init_agg_kernel<<<(int)((total + 255) / 256), 256>>>(tmp, B[L], dinv, agg, N, Fout);

        const long sthreads = (long)E * 32;
        scatter_kernel<<<(int)((sthreads + 255) / 256), 256>>>(tmp, src, dstp, dinv, agg, E, Fout);

        in_act = agg;  // relu fused into next gemm's A load
    }
}

// round 5
// speedup vs baseline: 1.6981x; 1.6981x over previous
#include <cuda_runtime.h>
#include <cstdint>

#define N_NODES 100000
#define MAX_E   1600000
#define MAX_F   200

// Scratch (allocation-free rule: __device__ globals)
__device__ float g_tmp [N_NODES * MAX_F];   // GEMM output of current layer
__device__ float g_bufA[N_NODES * MAX_F];   // activations ping
__device__ float g_bufB[N_NODES * MAX_F];   // activations pong
__device__ float g_dinv[N_NODES];
__device__ int   g_deg [N_NODES];           // in-degree (edges only)
__device__ int   g_rowptr[N_NODES + 1];
__device__ int   g_cursor[N_NODES];
__device__ int   g_srcs[MAX_E];             // CSR-by-dst: source node ids

// ---------------------------------------------------------------------------
// degree / normalization / CSR build
// ---------------------------------------------------------------------------
__global__ void deg_zero_kernel(int* deg, int n) {
    int i = blockIdx.x * blockDim.x + threadIdx.x;
    if (i < n) deg[i] = 0;
}

__global__ void deg_count_kernel(const int* __restrict__ dst, int* deg, int E) {
    int e = blockIdx.x * blockDim.x + threadIdx.x;
    if (e < E) atomicAdd(&deg[dst[e]], 1);
}

__global__ void dinv_kernel(const int* __restrict__ deg, float* dinv, int n) {
    int i = blockIdx.x * blockDim.x + threadIdx.x;
    if (i < n) dinv[i] = rsqrtf((float)(deg[i] + 1));  // +1 self loop
}

// single-block exclusive scan of deg -> rowptr (and cursor copy)
__global__ void scan_kernel(const int* __restrict__ deg, int* rowptr, int* cursor, int n) {
    __shared__ int partial[1024];
    const int t = threadIdx.x;
    const int chunk = (n + 1023) / 1024;
    const int lo = t * chunk;
    const int hi = min(lo + chunk, n);
    int s = 0;
    for (int j = lo; j < hi; j++) s += deg[j];
    partial[t] = s;
    __syncthreads();
    // Hillis-Steele inclusive scan
    for (int off = 1; off < 1024; off <<= 1) {
        int v = (t >= off) ? partial[t - off] : 0;
        __syncthreads();
        partial[t] += v;
        __syncthreads();
    }
    int base = (t == 0) ? 0 : partial[t - 1];
    for (int j = lo; j < hi; j++) {
        rowptr[j] = base;
        cursor[j] = base;
        base += deg[j];
    }
    if (t == 1023) rowptr[n] = partial[1023];
}

__global__ void fill_kernel(const int* __restrict__ src, const int* __restrict__ dst,
                            int* cursor, int* srcs, int E) {
    int e = blockIdx.x * blockDim.x + threadIdx.x;
    if (e < E) {
        int pos = atomicAdd(&cursor[dst[e]], 1);
        srcs[pos] = src[e];
    }
}

// ---------------------------------------------------------------------------
// GEMM: C[M,N] = (relu?)A[M,K] @ W[K,N]
// 128x128 blocktile, BK=16, 256 threads, 8x8 microtile (4+4 split, conflict-free)
// ---------------------------------------------------------------------------
template<int DO_RELU>
__global__ __launch_bounds__(256, 2)
void gemm128_kernel(const float* __restrict__ A, const float* __restrict__ W,
                    float* __restrict__ C, int M, int K, int N) {
    __shared__ float As[16][132];
    __shared__ float Bs[16][132];

    const int tid = threadIdx.x;
    const int tx = tid & 15;
    const int ty = tid >> 4;
    const int row0 = blockIdx.y * 128;
    const int col0 = blockIdx.x * 128;

    const int ar = tid >> 1;         // 0..127
    const int ac = (tid & 1) * 8;    // 0 or 8
    const int br = tid >> 4;         // 0..15
    const int bc = (tid & 15) * 8;   // 0..120

    float acc[8][8];
#pragma unroll
    for (int i = 0; i < 8; i++)
#pragma unroll
        for (int j = 0; j < 8; j++) acc[i][j] = 0.0f;

    for (int k0 = 0; k0 < K; k0 += 16) {
        const int garow = row0 + ar;
        const bool arow_ok = (garow < M);
#pragma unroll
        for (int i = 0; i < 8; i++) {
            const int gk = k0 + ac + i;
            float v = 0.0f;
            if (arow_ok && gk < K) v = A[(long)garow * K + gk];
            if (DO_RELU) v = fmaxf(v, 0.0f);
            As[ac + i][ar] = v;
        }
        const int gbk = k0 + br;
        const bool bk_ok = (gbk < K);
#pragma unroll
        for (int i = 0; i < 8; i++) {
            const int gn = col0 + bc + i;
            float v = 0.0f;
            if (bk_ok && gn < N) v = W[(long)gbk * N + gn];
            Bs[br][bc + i] = v;
        }
        __syncthreads();

#pragma unroll
        for (int kk = 0; kk < 16; kk++) {
            float a[8], b[8];
#pragma unroll
            for (int i = 0; i < 4; i++) {
                a[i]     = As[kk][ty * 4 + i];
                a[4 + i] = As[kk][64 + ty * 4 + i];
            }
#pragma unroll
            for (int j = 0; j < 4; j++) {
                b[j]     = Bs[kk][tx * 4 + j];
                b[4 + j] = Bs[kk][64 + tx * 4 + j];
            }
#pragma unroll
            for (int i = 0; i < 8; i++)
#pragma unroll
                for (int j = 0; j < 8; j++)
                    acc[i][j] = fmaf(a[i], b[j], acc[i][j]);
        }
        __syncthreads();
    }

    const bool n_vec = ((N & 3) == 0);  // float4-store alignment requires N%4==0
#pragma unroll
    for (int ig = 0; ig < 2; ig++) {
#pragma unroll
        for (int ii = 0; ii < 4; ii++) {
            const int r = row0 + ig * 64 + ty * 4 + ii;
            if (r >= M) continue;
            const int i = ig * 4 + ii;
#pragma unroll
            for (int jg = 0; jg < 2; jg++) {
                const int c = col0 + jg * 64 + tx * 4;
                float* p = &C[(long)r * N + c];
                if (n_vec && c + 3 < N) {
                    *(float4*)p = make_float4(acc[i][jg * 4 + 0], acc[i][jg * 4 + 1],
                                              acc[i][jg * 4 + 2], acc[i][jg * 4 + 3]);
                } else {
#pragma unroll
                    for (int jj = 0; jj < 4; jj++)
                        if (c + jj < N) p[jj] = acc[i][jg * 4 + jj];
                }
            }
        }
    }
}

// ---------------------------------------------------------------------------
// gather: one warp per node.
//   out[i][f] = dinv[i] * ( dinv[i]*t[i][f] + sum_{e in CSR(i)} dinv[src]*t[src][f] ) + b[f]
// ---------------------------------------------------------------------------
template<int NF>
__global__ __launch_bounds__(256)
void gather_kernel(const float* __restrict__ t,
                   const int* __restrict__ rowptr,
                   const int* __restrict__ srcs,
                   const float* __restrict__ dinv,
                   const float* __restrict__ bias,
                   float* __restrict__ out, int n, int F) {
    const int warp = (blockIdx.x * blockDim.x + threadIdx.x) >> 5;
    const int lane = threadIdx.x & 31;
    if (warp >= n) return;
    const int i = warp;

    const float di = dinv[i];
    float sums[NF];
    {
        const float* trow = t + (long)i * F;
#pragma unroll
        for (int r = 0; r < NF; r++) {
            const int f = lane + r * 32;
            sums[r] = (f < F) ? di * trow[f] : 0.0f;
        }
    }

    const int e0 = rowptr[i];
    const int e1 = rowptr[i + 1];
    int e = e0;
    for (; e + 1 < e1; e += 2) {
        const int s0 = srcs[e];
        const int s1 = srcs[e + 1];
        const float w0 = dinv[s0];
        const float w1 = dinv[s1];
        const float* r0 = t + (long)s0 * F;
        const float* r1 = t + (long)s1 * F;
#pragma unroll
        for (int r = 0; r < NF; r++) {
            const int f = lane + r * 32;
            if (f < F) {
                float v0 = r0[f];
                float v1 = r1[f];
                sums[r] = fmaf(w0, v0, sums[r]);
                sums[r] = fmaf(w1, v1, sums[r]);
            }
        }
    }
    if (e < e1) {
        const int s0 = srcs[e];
        const float w0 = dinv[s0];
        const float* r0 = t + (long)s0 * F;
#pragma unroll
        for (int r = 0; r < NF; r++) {
            const int f = lane + r * 32;
            if (f < F) sums[r] = fmaf(w0, r0[f], sums[r]);
        }
    }

    float* orow = out + (long)i * F;
#pragma unroll
    for (int r = 0; r < NF; r++) {
        const int f = lane + r * 32;
        if (f < F) orow[f] = fmaf(di, sums[r], bias[f]);
    }
}

// ---------------------------------------------------------------------------
// host
// ---------------------------------------------------------------------------
static void launch_gather(const float* t, const int* rowptr, const int* srcs,
                          const float* dinv, const float* bias, float* out,
                          int n, int F) {
    const int blocks = (n + 7) / 8;  // 8 warps per 256-thread block
    switch ((F + 31) / 32) {
        case 2: gather_kernel<2><<<blocks, 256>>>(t, rowptr, srcs, dinv, bias, out, n, F); break;
        case 3: gather_kernel<3><<<blocks, 256>>>(t, rowptr, srcs, dinv, bias, out, n, F); break;
        case 4: gather_kernel<4><<<blocks, 256>>>(t, rowptr, srcs, dinv, bias, out, n, F); break;
        case 6: gather_kernel<6><<<blocks, 256>>>(t, rowptr, srcs, dinv, bias, out, n, F); break;
        default: gather_kernel<7><<<blocks, 256>>>(t, rowptr, srcs, dinv, bias, out, n, F); break;
    }
}

extern "C" void kernel_launch(void* const* d_in, const int* in_sizes, int n_in,
                              void* d_out, int out_size) {
    const float* x   = (const float*)d_in[0];
    const int* eidx  = (const int*)d_in[1];
    const int E      = in_sizes[1] / 2;
    const int* srcp  = eidx;
    const int* dstp  = eidx + E;

    const float* W[5] = { (const float*)d_in[2], (const float*)d_in[4],
                          (const float*)d_in[6], (const float*)d_in[8],
                          (const float*)d_in[10] };
    const float* B[5] = { (const float*)d_in[3], (const float*)d_in[5],
                          (const float*)d_in[7], (const float*)d_in[9],
                          (const float*)d_in[11] };
    const int dims[6] = {512, 200, 175, 125, 75, 50};
    const int N = N_NODES;

    float *tmp, *bufA, *bufB, *dinv;
    int *deg, *rowptr, *cursor, *srcs;
    cudaGetSymbolAddress((void**)&tmp,    g_tmp);
    cudaGetSymbolAddress((void**)&bufA,   g_bufA);
    cudaGetSymbolAddress((void**)&bufB,   g_bufB);
    cudaGetSymbolAddress((void**)&dinv,   g_dinv);
    cudaGetSymbolAddress((void**)&deg,    g_deg);
    cudaGetSymbolAddress((void**)&rowptr, g_rowptr);
    cudaGetSymbolAddress((void**)&cursor, g_cursor);
    cudaGetSymbolAddress((void**)&srcs,   g_srcs);

    // normalization + CSR build (per call; graph-capturable)
    deg_zero_kernel<<<(N + 255) / 256, 256>>>(deg, N);
    deg_count_kernel<<<(E + 255) / 256, 256>>>(dstp, deg, E);
    dinv_kernel<<<(N + 255) / 256, 256>>>(deg, dinv, N);
    scan_kernel<<<1, 1024>>>(deg, rowptr, cursor, N);
    fill_kernel<<<(E + 255) / 256, 256>>>(srcp, dstp, cursor, srcs, E);

    const float* in_act = x;
    float* outs[5] = { bufA, bufB, bufA, bufB, (float*)d_out };

    for (int L = 0; L < 5; L++) {
        const int Fin = dims[L], Fout = dims[L + 1];
        dim3 ggrid((Fout + 127) / 128, (N + 127) / 128);
        if (L == 0)
            gemm128_kernel<0><<<ggrid, 256>>>(in_act, W[L], tmp, N, Fin, Fout);
        else
            gemm128_kernel<1><<<ggrid, 256>>>(in_act, W[L], tmp, N, Fin, Fout);

        launch_gather(tmp, rowptr, srcs, dinv, B[L], outs[L], N, Fout);
        in_act = outs[L];
    }
}

// round 6
// speedup vs baseline: 1.8531x; 1.0912x over previous
#include <cuda_runtime.h>
#include <cstdint>

#define N_NODES 100000
#define MAX_E   1600000
#define MAX_F   200

// Scratch (allocation-free rule: __device__ globals)
__device__ float g_tmp [N_NODES * MAX_F];   // GEMM output (padded stride)
__device__ float g_bufA[N_NODES * MAX_F];   // activations ping (unpadded)
__device__ float g_bufB[N_NODES * MAX_F];   // activations pong (unpadded)
__device__ float g_dinv[N_NODES];
__device__ int   g_deg [N_NODES];
__device__ int   g_rowptr[N_NODES + 1];
__device__ int   g_cursor[N_NODES];
__device__ int   g_srcs[MAX_E];             // CSR-by-dst: source node ids
__device__ int   g_bsums[512];

// ---------------------------------------------------------------------------
// degree / normalization
// ---------------------------------------------------------------------------
__global__ void deg_zero_kernel(int* deg, int n) {
    int i = blockIdx.x * blockDim.x + threadIdx.x;
    if (i < n) deg[i] = 0;
}

__global__ void deg_count_kernel(const int* __restrict__ dst, int* deg, int E) {
    int e = blockIdx.x * blockDim.x + threadIdx.x;
    if (e < E) atomicAdd(&deg[dst[e]], 1);
}

__global__ void dinv_kernel(const int* __restrict__ deg, float* dinv, int n) {
    int i = blockIdx.x * blockDim.x + threadIdx.x;
    if (i < n) dinv[i] = rsqrtf((float)(deg[i] + 1));  // +1 self loop
}

// ---------------------------------------------------------------------------
// multi-block exclusive scan of deg -> rowptr / cursor  (3 phases)
// ---------------------------------------------------------------------------
__global__ void blocksum_kernel(const int* __restrict__ deg, int* bsums, int n) {
    __shared__ int sh[256];
    const int i = blockIdx.x * 256 + threadIdx.x;
    sh[threadIdx.x] = (i < n) ? deg[i] : 0;
    __syncthreads();
#pragma unroll
    for (int s = 128; s > 0; s >>= 1) {
        if (threadIdx.x < s) sh[threadIdx.x] += sh[threadIdx.x + s];
        __syncthreads();
    }
    if (threadIdx.x == 0) bsums[blockIdx.x] = sh[0];
}

// single block of 512 threads scans up to 512 block sums (exclusive, in place)
__global__ void scan_bsums_kernel(int* bsums, int nb, int* rowptr, int n) {
    __shared__ int sh[512];
    const int t = threadIdx.x;
    sh[t] = (t < nb) ? bsums[t] : 0;
    __syncthreads();
#pragma unroll
    for (int off = 1; off < 512; off <<= 1) {
        int u = (t >= off) ? sh[t - off] : 0;
        __syncthreads();
        sh[t] += u;
        __syncthreads();
    }
    if (t < nb) bsums[t] = (t == 0) ? 0 : sh[t - 1];
    if (t == 511) rowptr[n] = sh[511];   // total edge count
}

__global__ void local_scan_kernel(const int* __restrict__ deg, const int* __restrict__ boff,
                                  int* rowptr, int* cursor, int n) {
    __shared__ int sh[256];
    const int i = blockIdx.x * 256 + threadIdx.x;
    const int t = threadIdx.x;
    sh[t] = (i < n) ? deg[i] : 0;
    __syncthreads();
#pragma unroll
    for (int off = 1; off < 256; off <<= 1) {
        int u = (t >= off) ? sh[t - off] : 0;
        __syncthreads();
        sh[t] += u;
        __syncthreads();
    }
    if (i < n) {
        const int excl = boff[blockIdx.x] + ((t == 0) ? 0 : sh[t - 1]);
        rowptr[i] = excl;
        cursor[i] = excl;
    }
}

__global__ void fill_kernel(const int* __restrict__ src, const int* __restrict__ dst,
                            int* cursor, int* srcs, int E) {
    int e = blockIdx.x * blockDim.x + threadIdx.x;
    if (e < E) {
        int pos = atomicAdd(&cursor[dst[e]], 1);
        srcs[pos] = src[e];
    }
}

// ---------------------------------------------------------------------------
// GEMM: C[M,ldc] = (relu?)A[M,K] @ W[K,N]  -- C has padded stride ldc (%4==0);
// columns [N, ldc) come out as exact zeros (B-tile guard zero-fills gn >= N).
// 128x128 blocktile, BK=16, 256 threads, 8x8 microtile (4+4 split)
// ---------------------------------------------------------------------------
template<int DO_RELU>
__global__ __launch_bounds__(256, 2)
void gemm128_kernel(const float* __restrict__ A, const float* __restrict__ W,
                    float* __restrict__ C, int M, int K, int N, int ldc) {
    __shared__ float As[16][132];
    __shared__ float Bs[16][132];

    const int tid = threadIdx.x;
    const int tx = tid & 15;
    const int ty = tid >> 4;
    const int row0 = blockIdx.y * 128;
    const int col0 = blockIdx.x * 128;

    const int ar = tid >> 1;         // 0..127
    const int ac = (tid & 1) * 8;    // 0 or 8
    const int br = tid >> 4;         // 0..15
    const int bc = (tid & 15) * 8;   // 0..120

    float acc[8][8];
#pragma unroll
    for (int i = 0; i < 8; i++)
#pragma unroll
        for (int j = 0; j < 8; j++) acc[i][j] = 0.0f;

    for (int k0 = 0; k0 < K; k0 += 16) {
        const int garow = row0 + ar;
        const bool arow_ok = (garow < M);
#pragma unroll
        for (int i = 0; i < 8; i++) {
            const int gk = k0 + ac + i;
            float v = 0.0f;
            if (arow_ok && gk < K) v = A[(long)garow * K + gk];
            if (DO_RELU) v = fmaxf(v, 0.0f);
            As[ac + i][ar] = v;
        }
        const int gbk = k0 + br;
        const bool bk_ok = (gbk < K);
#pragma unroll
        for (int i = 0; i < 8; i++) {
            const int gn = col0 + bc + i;
            float v = 0.0f;
            if (bk_ok && gn < N) v = W[(long)gbk * N + gn];
            Bs[br][bc + i] = v;
        }
        __syncthreads();

#pragma unroll
        for (int kk = 0; kk < 16; kk++) {
            float a[8], b[8];
#pragma unroll
            for (int i = 0; i < 4; i++) {
                a[i]     = As[kk][ty * 4 + i];
                a[4 + i] = As[kk][64 + ty * 4 + i];
            }
#pragma unroll
            for (int j = 0; j < 4; j++) {
                b[j]     = Bs[kk][tx * 4 + j];
                b[4 + j] = Bs[kk][64 + tx * 4 + j];
            }
#pragma unroll
            for (int i = 0; i < 8; i++)
#pragma unroll
                for (int j = 0; j < 8; j++)
                    acc[i][j] = fmaf(a[i], b[j], acc[i][j]);
        }
        __syncthreads();
    }

    // store to padded C (ldc%4==0, col addresses 16B aligned -> always float4)
#pragma unroll
    for (int ig = 0; ig < 2; ig++) {
#pragma unroll
        for (int ii = 0; ii < 4; ii++) {
            const int r = row0 + ig * 64 + ty * 4 + ii;
            if (r >= M) continue;
            const int i = ig * 4 + ii;
#pragma unroll
            for (int jg = 0; jg < 2; jg++) {
                const int c = col0 + jg * 64 + tx * 4;
                if (c < ldc) {
                    float* p = &C[(long)r * ldc + c];
                    if (c + 3 < ldc) {
                        *(float4*)p = make_float4(acc[i][jg * 4 + 0], acc[i][jg * 4 + 1],
                                                  acc[i][jg * 4 + 2], acc[i][jg * 4 + 3]);
                    } else {
#pragma unroll
                        for (int jj = 0; jj < 4; jj++)
                            if (c + jj < ldc) p[jj] = acc[i][jg * 4 + jj];
                    }
                }
            }
        }
    }
}

// ---------------------------------------------------------------------------
// gather: one warp per node, float4 loads over padded rows (ldc%4==0).
//   out[i][f] = dinv[i]*( dinv[i]*t[i][f] + sum_e dinv[src]*t[src][f] ) + b[f]
// out is unpadded (stride F).
// ---------------------------------------------------------------------------
template<int NR>
__global__ __launch_bounds__(256)
void gather4_kernel(const float* __restrict__ t,
                    const int* __restrict__ rowptr,
                    const int* __restrict__ srcs,
                    const float* __restrict__ dinv,
                    const float* __restrict__ bias,
                    float* __restrict__ out, int n, int F, int ldc) {
    const int warp = (blockIdx.x * blockDim.x + threadIdx.x) >> 5;
    const int lane = threadIdx.x & 31;
    if (warp >= n) return;
    const int i = warp;
    const int nq = ldc >> 2;          // float4s per row

    const float di = dinv[i];
    float4 sums[NR];
    {
        const float4* trow = (const float4*)(t + (long)i * ldc);
#pragma unroll
        for (int r = 0; r < NR; r++) {
            const int q = lane + r * 32;
            if (q < nq) {
                float4 v = trow[q];
                sums[r] = make_float4(di * v.x, di * v.y, di * v.z, di * v.w);
            } else {
                sums[r] = make_float4(0.f, 0.f, 0.f, 0.f);
            }
        }
    }

    const int e0 = rowptr[i];
    const int e1 = rowptr[i + 1];
    int e = e0;
    for (; e + 1 < e1; e += 2) {
        const int s0 = srcs[e];
        const int s1 = srcs[e + 1];
        const float w0 = dinv[s0];
        const float w1 = dinv[s1];
        const float4* r0 = (const float4*)(t + (long)s0 * ldc);
        const float4* r1 = (const float4*)(t + (long)s1 * ldc);
#pragma unroll
        for (int r = 0; r < NR; r++) {
            const int q = lane + r * 32;
            if (q < nq) {
                float4 v0 = r0[q];
                float4 v1 = r1[q];
                sums[r].x = fmaf(w0, v0.x, sums[r].x);
                sums[r].y = fmaf(w0, v0.y, sums[r].y);
                sums[r].z = fmaf(w0, v0.z, sums[r].z);
                sums[r].w = fmaf(w0, v0.w, sums[r].w);
                sums[r].x = fmaf(w1, v1.x, sums[r].x);
                sums[r].y = fmaf(w1, v1.y, sums[r].y);
                sums[r].z = fmaf(w1, v1.z, sums[r].z);
                sums[r].w = fmaf(w1, v1.w, sums[r].w);
            }
        }
    }
    if (e < e1) {
        const int s0 = srcs[e];
        const float w0 = dinv[s0];
        const float4* r0 = (const float4*)(t + (long)s0 * ldc);
#pragma unroll
        for (int r = 0; r < NR; r++) {
            const int q = lane + r * 32;
            if (q < nq) {
                float4 v0 = r0[q];
                sums[r].x = fmaf(w0, v0.x, sums[r].x);
                sums[r].y = fmaf(w0, v0.y, sums[r].y);
                sums[r].z = fmaf(w0, v0.z, sums[r].z);
                sums[r].w = fmaf(w0, v0.w, sums[r].w);
            }
        }
    }

    float* orow = out + (long)i * F;
#pragma unroll
    for (int r = 0; r < NR; r++) {
        const int q = lane + r * 32;
        if (q < nq) {
            const int f = q * 4;
            const float s4[4] = { sums[r].x, sums[r].y, sums[r].z, sums[r].w };
#pragma unroll
            for (int c = 0; c < 4; c++) {
                const int ff = f + c;
                if (ff < F) orow[ff] = fmaf(di, s4[c], bias[ff]);
            }
        }
    }
}

// ---------------------------------------------------------------------------
// host
// ---------------------------------------------------------------------------
static void launch_gather(const float* t, const int* rowptr, const int* srcs,
                          const float* dinv, const float* bias, float* out,
                          int n, int F, int ldc) {
    const int blocks = (n + 7) / 8;  // 8 warps per 256-thread block
    const int nq = ldc / 4;
    if (nq > 32)
        gather4_kernel<2><<<blocks, 256>>>(t, rowptr, srcs, dinv, bias, out, n, F, ldc);
    else
        gather4_kernel<1><<<blocks, 256>>>(t, rowptr, srcs, dinv, bias, out, n, F, ldc);
}

extern "C" void kernel_launch(void* const* d_in, const int* in_sizes, int n_in,
                              void* d_out, int out_size) {
    const float* x   = (const float*)d_in[0];
    const int* eidx  = (const int*)d_in[1];
    const int E      = in_sizes[1] / 2;
    const int* srcp  = eidx;
    const int* dstp  = eidx + E;

    const float* W[5] = { (const float*)d_in[2], (const float*)d_in[4],
                          (const float*)d_in[6], (const float*)d_in[8],
                          (const float*)d_in[10] };
    const float* B[5] = { (const float*)d_in[3], (const float*)d_in[5],
                          (const float*)d_in[7], (const float*)d_in[9],
                          (const float*)d_in[11] };
    const int dims[6] = {512, 200, 175, 125, 75, 50};
    const int N = N_NODES;

    float *tmp, *bufA, *bufB, *dinv;
    int *deg, *rowptr, *cursor, *srcs, *bsums;
    cudaGetSymbolAddress((void**)&tmp,    g_tmp);
    cudaGetSymbolAddress((void**)&bufA,   g_bufA);
    cudaGetSymbolAddress((void**)&bufB,   g_bufB);
    cudaGetSymbolAddress((void**)&dinv,   g_dinv);
    cudaGetSymbolAddress((void**)&deg,    g_deg);
    cudaGetSymbolAddress((void**)&rowptr, g_rowptr);
    cudaGetSymbolAddress((void**)&cursor, g_cursor);
    cudaGetSymbolAddress((void**)&srcs,   g_srcs);
    cudaGetSymbolAddress((void**)&bsums,  g_bsums);

    // normalization + CSR build (multi-block scan)
    const int nb = (N + 255) / 256;  // 391
    deg_zero_kernel<<<(N + 255) / 256, 256>>>(deg, N);
    deg_count_kernel<<<(E + 255) / 256, 256>>>(dstp, deg, E);
    dinv_kernel<<<(N + 255) / 256, 256>>>(deg, dinv, N);
    blocksum_kernel<<<nb, 256>>>(deg, bsums, N);
    scan_bsums_kernel<<<1, 512>>>(bsums, nb, rowptr, N);
    local_scan_kernel<<<nb, 256>>>(deg, bsums, rowptr, cursor, N);
    fill_kernel<<<(E + 255) / 256, 256>>>(srcp, dstp, cursor, srcs, E);

    const float* in_act = x;
    float* outs[5] = { bufA, bufB, bufA, bufB, (float*)d_out };

    for (int L = 0; L < 5; L++) {
        const int Fin = dims[L], Fout = dims[L + 1];
        const int ldc = (Fout + 3) & ~3;   // padded stride, %4 == 0
        dim3 ggrid((ldc + 127) / 128, (N + 127) / 128);
        if (L == 0)
            gemm128_kernel<0><<<ggrid, 256>>>(in_act, W[L], tmp, N, Fin, Fout, ldc);
        else
            gemm128_kernel<1><<<ggrid, 256>>>(in_act, W[L], tmp, N, Fin, Fout, ldc);

        launch_gather(tmp, rowptr, srcs, dinv, B[L], outs[L], N, Fout, ldc);
        in_act = outs[L];
    }
}

// round 14
// speedup vs baseline: 2.6796x; 1.4461x over previous
#include <cuda_runtime.h>
#include <cuda_bf16.h>
#include <cstdint>

#define N_NODES 100000
#define MAX_E   1600000
#define MAX_F   200

// Scratch (allocation-free rule: __device__ globals)
__device__ float g_tmp [N_NODES * MAX_F];   // GEMM output (padded stride)
__device__ float g_bufA[N_NODES * MAX_F];   // activations ping (unpadded)
__device__ float g_bufB[N_NODES * MAX_F];   // activations pong (unpadded)
__device__ float g_dinv[N_NODES];
__device__ int   g_deg [N_NODES];
__device__ int   g_rowptr[N_NODES + 1];
__device__ int   g_cursor[N_NODES];
__device__ int   g_srcs[MAX_E];             // CSR-by-dst: source node ids
__device__ int   g_bsums[512];

// ---------------------------------------------------------------------------
// degree / normalization
// ---------------------------------------------------------------------------
__global__ void deg_zero_kernel(int* deg, int n) {
    int i = blockIdx.x * blockDim.x + threadIdx.x;
    if (i < n) deg[i] = 0;
}

__global__ void deg_count_kernel(const int* __restrict__ dst, int* deg, int E) {
    int e = blockIdx.x * blockDim.x + threadIdx.x;
    if (e < E) atomicAdd(&deg[dst[e]], 1);
}

__global__ void dinv_kernel(const int* __restrict__ deg, float* dinv, int n) {
    int i = blockIdx.x * blockDim.x + threadIdx.x;
    if (i < n) dinv[i] = rsqrtf((float)(deg[i] + 1));  // +1 self loop
}

// ---------------------------------------------------------------------------
// multi-block exclusive scan of deg -> rowptr / cursor  (3 phases)
// ---------------------------------------------------------------------------
__global__ void blocksum_kernel(const int* __restrict__ deg, int* bsums, int n) {
    __shared__ int sh[256];
    const int i = blockIdx.x * 256 + threadIdx.x;
    sh[threadIdx.x] = (i < n) ? deg[i] : 0;
    __syncthreads();
#pragma unroll
    for (int s = 128; s > 0; s >>= 1) {
        if (threadIdx.x < s) sh[threadIdx.x] += sh[threadIdx.x + s];
        __syncthreads();
    }
    if (threadIdx.x == 0) bsums[blockIdx.x] = sh[0];
}

__global__ void scan_bsums_kernel(int* bsums, int nb, int* rowptr, int n) {
    __shared__ int sh[512];
    const int t = threadIdx.x;
    sh[t] = (t < nb) ? bsums[t] : 0;
    __syncthreads();
#pragma unroll
    for (int off = 1; off < 512; off <<= 1) {
        int u = (t >= off) ? sh[t - off] : 0;
        __syncthreads();
        sh[t] += u;
        __syncthreads();
    }
    if (t < nb) bsums[t] = (t == 0) ? 0 : sh[t - 1];
    if (t == 511) rowptr[n] = sh[511];
}

__global__ void local_scan_kernel(const int* __restrict__ deg, const int* __restrict__ boff,
                                  int* rowptr, int* cursor, int n) {
    __shared__ int sh[256];
    const int i = blockIdx.x * 256 + threadIdx.x;
    const int t = threadIdx.x;
    sh[t] = (i < n) ? deg[i] : 0;
    __syncthreads();
#pragma unroll
    for (int off = 1; off < 256; off <<= 1) {
        int u = (t >= off) ? sh[t - off] : 0;
        __syncthreads();
        sh[t] += u;
        __syncthreads();
    }
    if (i < n) {
        const int excl = boff[blockIdx.x] + ((t == 0) ? 0 : sh[t - 1]);
        rowptr[i] = excl;
        cursor[i] = excl;
    }
}

__global__ void fill_kernel(const int* __restrict__ src, const int* __restrict__ dst,
                            int* cursor, int* srcs, int E) {
    int e = blockIdx.x * blockDim.x + threadIdx.x;
    if (e < E) {
        int pos = atomicAdd(&cursor[dst[e]], 1);
        srcs[pos] = src[e];
    }
}

// ---------------------------------------------------------------------------
// bf16-split tensor-core GEMM:
//   C[M,ldc] = (relu?)A[M,K] @ W[K,N]  in fp32-equivalent precision via
//   A = Ahi + Alo (bf16), W = Whi + Wlo (bf16);
//   C = Ahi*Whi + Ahi*Wlo + Alo*Whi   (lo*lo dropped, ~1e-5 rel err)
// Block tile 128(M) x 64(N), BK=32. 8 warps: 4(M) x 2(N), warp tile 32x32.
// mma.sync.aligned.m16n8k16.row.col.f32.bf16.bf16.f32
// Cols [N, ldc) are exact zeros (W guard zero-fills).
// ---------------------------------------------------------------------------
#define SMS 34   // smem k-stride (padded, even, bank-spread: 17 words per row)

__device__ __forceinline__ void mma_bf16(float* c, const uint32_t* a, const uint32_t* b) {
    asm volatile(
        "mma.sync.aligned.m16n8k16.row.col.f32.bf16.bf16.f32 "
        "{%0,%1,%2,%3}, {%4,%5,%6,%7}, {%8,%9}, {%0,%1,%2,%3};"
        : "+f"(c[0]), "+f"(c[1]), "+f"(c[2]), "+f"(c[3])
        : "r"(a[0]), "r"(a[1]), "r"(a[2]), "r"(a[3]), "r"(b[0]), "r"(b[1]));
}

template<int DO_RELU>
__global__ __launch_bounds__(256, 2)
void gemm_bf16x2_kernel(const float* __restrict__ A, const float* __restrict__ W,
                        float* __restrict__ C, int M, int K, int N, int ldc) {
    __shared__ __align__(16) unsigned short As_hi[128 * SMS];
    __shared__ __align__(16) unsigned short As_lo[128 * SMS];
    __shared__ __align__(16) unsigned short Bs_hi[64 * SMS];
    __shared__ __align__(16) unsigned short Bs_lo[64 * SMS];

    const int tid  = threadIdx.x;
    const int warp = tid >> 5;
    const int lane = tid & 31;
    const int gid  = lane >> 2;      // 0..7
    const int tig  = lane & 3;       // 0..3
    const int wm   = warp & 3;       // 0..3  (M)
    const int wn   = warp >> 2;      // 0..1  (N)

    const int row0 = blockIdx.y * 128;
    const int col0 = blockIdx.x * 64;

    float acc[2][4][4];
#pragma unroll
    for (int mt = 0; mt < 2; mt++)
#pragma unroll
        for (int nt = 0; nt < 4; nt++)
#pragma unroll
            for (int c = 0; c < 4; c++) acc[mt][nt][c] = 0.0f;

    for (int k0 = 0; k0 < K; k0 += 32) {
        // --- load A tile 128x32 fp32 -> split bf16 hi/lo ---
#pragma unroll
        for (int i = 0; i < 16; i++) {
            const int idx = tid + i * 256;         // 0..4095
            const int r  = idx >> 5;
            const int kk = idx & 31;
            const int gr = row0 + r;
            const int gk = k0 + kk;
            float v = 0.0f;
            if (gr < M && gk < K) v = A[(long)gr * K + gk];
            if (DO_RELU) v = fmaxf(v, 0.0f);
            __nv_bfloat16 hi = __float2bfloat16(v);
            __nv_bfloat16 lo = __float2bfloat16(v - __bfloat162float(hi));
            As_hi[r * SMS + kk] = *reinterpret_cast<unsigned short*>(&hi);
            As_lo[r * SMS + kk] = *reinterpret_cast<unsigned short*>(&lo);
        }
        // --- load W tile 32x64 fp32 -> transposed split bf16 Bs[n][k] ---
#pragma unroll
        for (int i = 0; i < 8; i++) {
            const int idx = tid + i * 256;         // 0..2047
            const int kk = idx >> 6;
            const int nn = idx & 63;
            const int gk = k0 + kk;
            const int gn = col0 + nn;
            float v = 0.0f;
            if (gk < K && gn < N) v = W[(long)gk * N + gn];
            __nv_bfloat16 hi = __float2bfloat16(v);
            __nv_bfloat16 lo = __float2bfloat16(v - __bfloat162float(hi));
            Bs_hi[nn * SMS + kk] = *reinterpret_cast<unsigned short*>(&hi);
            Bs_lo[nn * SMS + kk] = *reinterpret_cast<unsigned short*>(&lo);
        }
        __syncthreads();

#pragma unroll
        for (int ks = 0; ks < 2; ks++) {
            const int kb = ks * 16;
            uint32_t a_hi[2][4], a_lo[2][4], b_hi[4][2], b_lo[4][2];
#pragma unroll
            for (int mt = 0; mt < 2; mt++) {
                const int r = wm * 32 + mt * 16 + gid;
                const int kq = kb + 2 * tig;
                a_hi[mt][0] = *(const uint32_t*)&As_hi[(r)     * SMS + kq];
                a_hi[mt][1] = *(const uint32_t*)&As_hi[(r + 8) * SMS + kq];
                a_hi[mt][2] = *(const uint32_t*)&As_hi[(r)     * SMS + kq + 8];
                a_hi[mt][3] = *(const uint32_t*)&As_hi[(r + 8) * SMS + kq + 8];
                a_lo[mt][0] = *(const uint32_t*)&As_lo[(r)     * SMS + kq];
                a_lo[mt][1] = *(const uint32_t*)&As_lo[(r + 8) * SMS + kq];
                a_lo[mt][2] = *(const uint32_t*)&As_lo[(r)     * SMS + kq + 8];
                a_lo[mt][3] = *(const uint32_t*)&As_lo[(r + 8) * SMS + kq + 8];
            }
#pragma unroll
            for (int nt = 0; nt < 4; nt++) {
                const int nr = wn * 32 + nt * 8 + gid;
                const int kq = kb + 2 * tig;
                b_hi[nt][0] = *(const uint32_t*)&Bs_hi[nr * SMS + kq];
                b_hi[nt][1] = *(const uint32_t*)&Bs_hi[nr * SMS + kq + 8];
                b_lo[nt][0] = *(const uint32_t*)&Bs_lo[nr * SMS + kq];
                b_lo[nt][1] = *(const uint32_t*)&Bs_lo[nr * SMS + kq + 8];
            }
#pragma unroll
            for (int mt = 0; mt < 2; mt++)
#pragma unroll
                for (int nt = 0; nt < 4; nt++) {
                    mma_bf16(acc[mt][nt], a_hi[mt], b_hi[nt]);
                    mma_bf16(acc[mt][nt], a_hi[mt], b_lo[nt]);
                    mma_bf16(acc[mt][nt], a_lo[mt], b_hi[nt]);
                }
        }
        __syncthreads();
    }

    // --- epilogue: c-frag (gid rows, 2tig cols) -> padded C ---
#pragma unroll
    for (int mt = 0; mt < 2; mt++) {
#pragma unroll
        for (int nt = 0; nt < 4; nt++) {
            const int r  = row0 + wm * 32 + mt * 16 + gid;
            const int cc = col0 + wn * 32 + nt * 8 + 2 * tig;
            if (cc < ldc) {
                if (r < M) {
                    float2 v = make_float2(acc[mt][nt][0], acc[mt][nt][1]);
                    *(float2*)&C[(long)r * ldc + cc] = v;
                }
                if (r + 8 < M) {
                    float2 v = make_float2(acc[mt][nt][2], acc[mt][nt][3]);
                    *(float2*)&C[(long)(r + 8) * ldc + cc] = v;
                }
            }
        }
    }
}

// ---------------------------------------------------------------------------
// gather: one warp per node, float4 loads over padded rows (ldc%4==0).
//   out[i][f] = dinv[i]*( dinv[i]*t[i][f] + sum_e dinv[src]*t[src][f] ) + b[f]
// ---------------------------------------------------------------------------
template<int NR>
__global__ __launch_bounds__(256)
void gather4_kernel(const float* __restrict__ t,
                    const int* __restrict__ rowptr,
                    const int* __restrict__ srcs,
                    const float* __restrict__ dinv,
                    const float* __restrict__ bias,
                    float* __restrict__ out, int n, int F, int ldc) {
    const int warp = (blockIdx.x * blockDim.x + threadIdx.x) >> 5;
    const int lane = threadIdx.x & 31;
    if (warp >= n) return;
    const int i = warp;
    const int nq = ldc >> 2;

    const float di = dinv[i];
    float4 sums[NR];
    {
        const float4* trow = (const float4*)(t + (long)i * ldc);
#pragma unroll
        for (int r = 0; r < NR; r++) {
            const int q = lane + r * 32;
            if (q < nq) {
                float4 v = trow[q];
                sums[r] = make_float4(di * v.x, di * v.y, di * v.z, di * v.w);
            } else {
                sums[r] = make_float4(0.f, 0.f, 0.f, 0.f);
            }
        }
    }

    const int e0 = rowptr[i];
    const int e1 = rowptr[i + 1];
    int e = e0;
    for (; e + 1 < e1; e += 2) {
        const int s0 = srcs[e];
        const int s1 = srcs[e + 1];
        const float w0 = dinv[s0];
        const float w1 = dinv[s1];
        const float4* r0 = (const float4*)(t + (long)s0 * ldc);
        const float4* r1 = (const float4*)(t + (long)s1 * ldc);
#pragma unroll
        for (int r = 0; r < NR; r++) {
            const int q = lane + r * 32;
            if (q < nq) {
                float4 v0 = r0[q];
                float4 v1 = r1[q];
                sums[r].x = fmaf(w0, v0.x, sums[r].x);
                sums[r].y = fmaf(w0, v0.y, sums[r].y);
                sums[r].z = fmaf(w0, v0.z, sums[r].z);
                sums[r].w = fmaf(w0, v0.w, sums[r].w);
                sums[r].x = fmaf(w1, v1.x, sums[r].x);
                sums[r].y = fmaf(w1, v1.y, sums[r].y);
                sums[r].z = fmaf(w1, v1.z, sums[r].z);
                sums[r].w = fmaf(w1, v1.w, sums[r].w);
            }
        }
    }
    if (e < e1) {
        const int s0 = srcs[e];
        const float w0 = dinv[s0];
        const float4* r0 = (const float4*)(t + (long)s0 * ldc);
#pragma unroll
        for (int r = 0; r < NR; r++) {
            const int q = lane + r * 32;
            if (q < nq) {
                float4 v0 = r0[q];
                sums[r].x = fmaf(w0, v0.x, sums[r].x);
                sums[r].y = fmaf(w0, v0.y, sums[r].y);
                sums[r].z = fmaf(w0, v0.z, sums[r].z);
                sums[r].w = fmaf(w0, v0.w, sums[r].w);
            }
        }
    }

    float* orow = out + (long)i * F;
#pragma unroll
    for (int r = 0; r < NR; r++) {
        const int q = lane + r * 32;
        if (q < nq) {
            const int f = q * 4;
            const float s4[4] = { sums[r].x, sums[r].y, sums[r].z, sums[r].w };
#pragma unroll
            for (int c = 0; c < 4; c++) {
                const int ff = f + c;
                if (ff < F) orow[ff] = fmaf(di, s4[c], bias[ff]);
            }
        }
    }
}

// ---------------------------------------------------------------------------
// host
// ---------------------------------------------------------------------------
static void launch_gather(const float* t, const int* rowptr, const int* srcs,
                          const float* dinv, const float* bias, float* out,
                          int n, int F, int ldc) {
    const int blocks = (n + 7) / 8;
    const int nq = ldc / 4;
    if (nq > 32)
        gather4_kernel<2><<<blocks, 256>>>(t, rowptr, srcs, dinv, bias, out, n, F, ldc);
    else
        gather4_kernel<1><<<blocks, 256>>>(t, rowptr, srcs, dinv, bias, out, n, F, ldc);
}

extern "C" void kernel_launch(void* const* d_in, const int* in_sizes, int n_in,
                              void* d_out, int out_size) {
    const float* x   = (const float*)d_in[0];
    const int* eidx  = (const int*)d_in[1];
    const int E      = in_sizes[1] / 2;
    const int* srcp  = eidx;
    const int* dstp  = eidx + E;

    const float* W[5] = { (const float*)d_in[2], (const float*)d_in[4],
                          (const float*)d_in[6], (const float*)d_in[8],
                          (const float*)d_in[10] };
    const float* B[5] = { (const float*)d_in[3], (const float*)d_in[5],
                          (const float*)d_in[7], (const float*)d_in[9],
                          (const float*)d_in[11] };
    const int dims[6] = {512, 200, 175, 125, 75, 50};
    const int N = N_NODES;

    float *tmp, *bufA, *bufB, *dinv;
    int *deg, *rowptr, *cursor, *srcs, *bsums;
    cudaGetSymbolAddress((void**)&tmp,    g_tmp);
    cudaGetSymbolAddress((void**)&bufA,   g_bufA);
    cudaGetSymbolAddress((void**)&bufB,   g_bufB);
    cudaGetSymbolAddress((void**)&dinv,   g_dinv);
    cudaGetSymbolAddress((void**)&deg,    g_deg);
    cudaGetSymbolAddress((void**)&rowptr, g_rowptr);
    cudaGetSymbolAddress((void**)&cursor, g_cursor);
    cudaGetSymbolAddress((void**)&srcs,   g_srcs);
    cudaGetSymbolAddress((void**)&bsums,  g_bsums);

    const int nb = (N + 255) / 256;  // 391
    deg_zero_kernel<<<(N + 255) / 256, 256>>>(deg, N);
    deg_count_kernel<<<(E + 255) / 256, 256>>>(dstp, deg, E);
    dinv_kernel<<<(N + 255) / 256, 256>>>(deg, dinv, N);
    blocksum_kernel<<<nb, 256>>>(deg, bsums, N);
    scan_bsums_kernel<<<1, 512>>>(bsums, nb, rowptr, N);
    local_scan_kernel<<<nb, 256>>>(deg, bsums, rowptr, cursor, N);
    fill_kernel<<<(E + 255) / 256, 256>>>(srcp, dstp, cursor, srcs, E);

    const float* in_act = x;
    float* outs[5] = { bufA, bufB, bufA, bufB, (float*)d_out };

    for (int L = 0; L < 5; L++) {
        const int Fin = dims[L], Fout = dims[L + 1];
        const int ldc = (Fout + 3) & ~3;   // padded stride, %4 == 0
        dim3 ggrid((ldc + 63) / 64, (N + 127) / 128);
        if (L == 0)
            gemm_bf16x2_kernel<0><<<ggrid, 256>>>(in_act, W[L], tmp, N, Fin, Fout, ldc);
        else
            gemm_bf16x2_kernel<1><<<ggrid, 256>>>(in_act, W[L], tmp, N, Fin, Fout, ldc);

        launch_gather(tmp, rowptr, srcs, dinv, B[L], outs[L], N, Fout, ldc);
        in_act = outs[L];
    }
}

// round 15
// speedup vs baseline: 2.8691x; 1.0707x over previous
#include <cuda_runtime.h>
#include <cuda_bf16.h>
#include <cstdint>

#define N_NODES 100000
#define MAX_E   1600000
#define MAX_F   200

// Scratch (allocation-free rule: __device__ globals)
__device__ float g_tmp [N_NODES * MAX_F];   // GEMM output, pre-scaled by dinv[row]
__device__ float g_bufA[N_NODES * MAX_F];   // activations ping (unpadded)
__device__ float g_bufB[N_NODES * MAX_F];   // activations pong (unpadded)
__device__ float g_dinv[N_NODES];
__device__ int   g_deg [N_NODES];
__device__ int   g_rowptr[N_NODES + 1];
__device__ int   g_cursor[N_NODES];
__device__ int   g_srcs[MAX_E];             // CSR-by-dst: source node ids
__device__ int   g_bsums[512];

// ---------------------------------------------------------------------------
// degree / normalization
// ---------------------------------------------------------------------------
__global__ void deg_zero_kernel(int* deg, int n) {
    int i = blockIdx.x * blockDim.x + threadIdx.x;
    if (i < n) deg[i] = 0;
}

__global__ void deg_count_kernel(const int* __restrict__ dst, int* deg, int E) {
    int e = blockIdx.x * blockDim.x + threadIdx.x;
    if (e < E) atomicAdd(&deg[dst[e]], 1);
}

__global__ void dinv_kernel(const int* __restrict__ deg, float* dinv, int n) {
    int i = blockIdx.x * blockDim.x + threadIdx.x;
    if (i < n) dinv[i] = rsqrtf((float)(deg[i] + 1));  // +1 self loop
}

// ---------------------------------------------------------------------------
// multi-block exclusive scan of deg -> rowptr / cursor  (3 phases)
// ---------------------------------------------------------------------------
__global__ void blocksum_kernel(const int* __restrict__ deg, int* bsums, int n) {
    __shared__ int sh[256];
    const int i = blockIdx.x * 256 + threadIdx.x;
    sh[threadIdx.x] = (i < n) ? deg[i] : 0;
    __syncthreads();
#pragma unroll
    for (int s = 128; s > 0; s >>= 1) {
        if (threadIdx.x < s) sh[threadIdx.x] += sh[threadIdx.x + s];
        __syncthreads();
    }
    if (threadIdx.x == 0) bsums[blockIdx.x] = sh[0];
}

__global__ void scan_bsums_kernel(int* bsums, int nb, int* rowptr, int n) {
    __shared__ int sh[512];
    const int t = threadIdx.x;
    sh[t] = (t < nb) ? bsums[t] : 0;
    __syncthreads();
#pragma unroll
    for (int off = 1; off < 512; off <<= 1) {
        int u = (t >= off) ? sh[t - off] : 0;
        __syncthreads();
        sh[t] += u;
        __syncthreads();
    }
    if (t < nb) bsums[t] = (t == 0) ? 0 : sh[t - 1];
    if (t == 511) rowptr[n] = sh[511];
}

__global__ void local_scan_kernel(const int* __restrict__ deg, const int* __restrict__ boff,
                                  int* rowptr, int* cursor, int n) {
    __shared__ int sh[256];
    const int i = blockIdx.x * 256 + threadIdx.x;
    const int t = threadIdx.x;
    sh[t] = (i < n) ? deg[i] : 0;
    __syncthreads();
#pragma unroll
    for (int off = 1; off < 256; off <<= 1) {
        int u = (t >= off) ? sh[t - off] : 0;
        __syncthreads();
        sh[t] += u;
        __syncthreads();
    }
    if (i < n) {
        const int excl = boff[blockIdx.x] + ((t == 0) ? 0 : sh[t - 1]);
        rowptr[i] = excl;
        cursor[i] = excl;
    }
}

__global__ void fill_kernel(const int* __restrict__ src, const int* __restrict__ dst,
                            int* cursor, int* srcs, int E) {
    int e = blockIdx.x * blockDim.x + threadIdx.x;
    if (e < E) {
        int pos = atomicAdd(&cursor[dst[e]], 1);
        srcs[pos] = src[e];
    }
}

// ---------------------------------------------------------------------------
// bf16-split tensor-core GEMM + dinv pre-scale epilogue:
//   C[M,ldc] = dinv[row] * ( (relu?)A[M,K] @ W[K,N] )
//   A = Ahi + Alo (bf16), W = Whi + Wlo (bf16);
//   product = Ahi*Whi + Ahi*Wlo + Alo*Whi   (lo*lo dropped, ~1e-5 rel err)
// Block tile 128(M) x 64(N), BK=32. 8 warps: 4(M) x 2(N), warp tile 32x32.
// mma.sync.aligned.m16n8k16.row.col.f32.bf16.bf16.f32
// Cols [N, ldc) are exact zeros (W guard zero-fills).
// ---------------------------------------------------------------------------
#define SMS 34   // smem k-stride (padded, even, bank-spread: 17 words per row)

__device__ __forceinline__ void mma_bf16(float* c, const uint32_t* a, const uint32_t* b) {
    asm volatile(
        "mma.sync.aligned.m16n8k16.row.col.f32.bf16.bf16.f32 "
        "{%0,%1,%2,%3}, {%4,%5,%6,%7}, {%8,%9}, {%0,%1,%2,%3};"
        : "+f"(c[0]), "+f"(c[1]), "+f"(c[2]), "+f"(c[3])
        : "r"(a[0]), "r"(a[1]), "r"(a[2]), "r"(a[3]), "r"(b[0]), "r"(b[1]));
}

template<int DO_RELU>
__global__ __launch_bounds__(256, 2)
void gemm_bf16x2_kernel(const float* __restrict__ A, const float* __restrict__ W,
                        const float* __restrict__ dinv,
                        float* __restrict__ C, int M, int K, int N, int ldc) {
    __shared__ __align__(16) unsigned short As_hi[128 * SMS];
    __shared__ __align__(16) unsigned short As_lo[128 * SMS];
    __shared__ __align__(16) unsigned short Bs_hi[64 * SMS];
    __shared__ __align__(16) unsigned short Bs_lo[64 * SMS];

    const int tid  = threadIdx.x;
    const int warp = tid >> 5;
    const int lane = tid & 31;
    const int gid  = lane >> 2;      // 0..7
    const int tig  = lane & 3;       // 0..3
    const int wm   = warp & 3;       // 0..3  (M)
    const int wn   = warp >> 2;      // 0..1  (N)

    const int row0 = blockIdx.y * 128;
    const int col0 = blockIdx.x * 64;

    float acc[2][4][4];
#pragma unroll
    for (int mt = 0; mt < 2; mt++)
#pragma unroll
        for (int nt = 0; nt < 4; nt++)
#pragma unroll
            for (int c = 0; c < 4; c++) acc[mt][nt][c] = 0.0f;

    for (int k0 = 0; k0 < K; k0 += 32) {
        // --- load A tile 128x32 fp32 -> split bf16 hi/lo ---
#pragma unroll
        for (int i = 0; i < 16; i++) {
            const int idx = tid + i * 256;         // 0..4095
            const int r  = idx >> 5;
            const int kk = idx & 31;
            const int gr = row0 + r;
            const int gk = k0 + kk;
            float v = 0.0f;
            if (gr < M && gk < K) v = A[(long)gr * K + gk];
            if (DO_RELU) v = fmaxf(v, 0.0f);
            __nv_bfloat16 hi = __float2bfloat16(v);
            __nv_bfloat16 lo = __float2bfloat16(v - __bfloat162float(hi));
            As_hi[r * SMS + kk] = *reinterpret_cast<unsigned short*>(&hi);
            As_lo[r * SMS + kk] = *reinterpret_cast<unsigned short*>(&lo);
        }
        // --- load W tile 32x64 fp32 -> transposed split bf16 Bs[n][k] ---
#pragma unroll
        for (int i = 0; i < 8; i++) {
            const int idx = tid + i * 256;         // 0..2047
            const int kk = idx >> 6;
            const int nn = idx & 63;
            const int gk = k0 + kk;
            const int gn = col0 + nn;
            float v = 0.0f;
            if (gk < K && gn < N) v = W[(long)gk * N + gn];
            __nv_bfloat16 hi = __float2bfloat16(v);
            __nv_bfloat16 lo = __float2bfloat16(v - __bfloat162float(hi));
            Bs_hi[nn * SMS + kk] = *reinterpret_cast<unsigned short*>(&hi);
            Bs_lo[nn * SMS + kk] = *reinterpret_cast<unsigned short*>(&lo);
        }
        __syncthreads();

#pragma unroll
        for (int ks = 0; ks < 2; ks++) {
            const int kb = ks * 16;
            uint32_t a_hi[2][4], a_lo[2][4], b_hi[4][2], b_lo[4][2];
#pragma unroll
            for (int mt = 0; mt < 2; mt++) {
                const int r = wm * 32 + mt * 16 + gid;
                const int kq = kb + 2 * tig;
                a_hi[mt][0] = *(const uint32_t*)&As_hi[(r)     * SMS + kq];
                a_hi[mt][1] = *(const uint32_t*)&As_hi[(r + 8) * SMS + kq];
                a_hi[mt][2] = *(const uint32_t*)&As_hi[(r)     * SMS + kq + 8];
                a_hi[mt][3] = *(const uint32_t*)&As_hi[(r + 8) * SMS + kq + 8];
                a_lo[mt][0] = *(const uint32_t*)&As_lo[(r)     * SMS + kq];
                a_lo[mt][1] = *(const uint32_t*)&As_lo[(r + 8) * SMS + kq];
                a_lo[mt][2] = *(const uint32_t*)&As_lo[(r)     * SMS + kq + 8];
                a_lo[mt][3] = *(const uint32_t*)&As_lo[(r + 8) * SMS + kq + 8];
            }
#pragma unroll
            for (int nt = 0; nt < 4; nt++) {
                const int nr = wn * 32 + nt * 8 + gid;
                const int kq = kb + 2 * tig;
                b_hi[nt][0] = *(const uint32_t*)&Bs_hi[nr * SMS + kq];
                b_hi[nt][1] = *(const uint32_t*)&Bs_hi[nr * SMS + kq + 8];
                b_lo[nt][0] = *(const uint32_t*)&Bs_lo[nr * SMS + kq];
                b_lo[nt][1] = *(const uint32_t*)&Bs_lo[nr * SMS + kq + 8];
            }
#pragma unroll
            for (int mt = 0; mt < 2; mt++)
#pragma unroll
                for (int nt = 0; nt < 4; nt++) {
                    mma_bf16(acc[mt][nt], a_hi[mt], b_hi[nt]);
                    mma_bf16(acc[mt][nt], a_hi[mt], b_lo[nt]);
                    mma_bf16(acc[mt][nt], a_lo[mt], b_hi[nt]);
                }
        }
        __syncthreads();
    }

    // --- epilogue: scale rows by dinv, store to padded C ---
#pragma unroll
    for (int mt = 0; mt < 2; mt++) {
        const int r = row0 + wm * 32 + mt * 16 + gid;
        const float d0 = (r < M)     ? dinv[r]     : 0.0f;
        const float d1 = (r + 8 < M) ? dinv[r + 8] : 0.0f;
#pragma unroll
        for (int nt = 0; nt < 4; nt++) {
            const int cc = col0 + wn * 32 + nt * 8 + 2 * tig;
            if (cc < ldc) {
                if (r < M) {
                    float2 v = make_float2(d0 * acc[mt][nt][0], d0 * acc[mt][nt][1]);
                    *(float2*)&C[(long)r * ldc + cc] = v;
                }
                if (r + 8 < M) {
                    float2 v = make_float2(d1 * acc[mt][nt][2], d1 * acc[mt][nt][3]);
                    *(float2*)&C[(long)(r + 8) * ldc + cc] = v;
                }
            }
        }
    }
}

// ---------------------------------------------------------------------------
// gather: one warp per node, float4 loads over padded pre-scaled rows.
//   S[i] = dinv[i]*t[i]  (stored in tmp by GEMM epilogue)
//   out[i][f] = dinv[i]*( S[i][f] + sum_e S[src][f] ) + b[f]
// 4-edge unroll for MLP.
// ---------------------------------------------------------------------------
template<int NR>
__global__ __launch_bounds__(256)
void gather4_kernel(const float* __restrict__ t,
                    const int* __restrict__ rowptr,
                    const int* __restrict__ srcs,
                    const float* __restrict__ dinv,
                    const float* __restrict__ bias,
                    float* __restrict__ out, int n, int F, int ldc) {
    const int warp = (blockIdx.x * blockDim.x + threadIdx.x) >> 5;
    const int lane = threadIdx.x & 31;
    if (warp >= n) return;
    const int i = warp;
    const int nq = ldc >> 2;

    float4 sums[NR];
    {
        const float4* trow = (const float4*)(t + (long)i * ldc);
#pragma unroll
        for (int r = 0; r < NR; r++) {
            const int q = lane + r * 32;
            sums[r] = (q < nq) ? trow[q] : make_float4(0.f, 0.f, 0.f, 0.f);
        }
    }

    const int e0 = rowptr[i];
    const int e1 = rowptr[i + 1];
    int e = e0;
    for (; e + 3 < e1; e += 4) {
        const int s0 = srcs[e];
        const int s1 = srcs[e + 1];
        const int s2 = srcs[e + 2];
        const int s3 = srcs[e + 3];
        const float4* r0 = (const float4*)(t + (long)s0 * ldc);
        const float4* r1 = (const float4*)(t + (long)s1 * ldc);
        const float4* r2 = (const float4*)(t + (long)s2 * ldc);
        const float4* r3 = (const float4*)(t + (long)s3 * ldc);
#pragma unroll
        for (int r = 0; r < NR; r++) {
            const int q = lane + r * 32;
            if (q < nq) {
                float4 v0 = r0[q];
                float4 v1 = r1[q];
                float4 v2 = r2[q];
                float4 v3 = r3[q];
                sums[r].x += v0.x + v1.x + v2.x + v3.x;
                sums[r].y += v0.y + v1.y + v2.y + v3.y;
                sums[r].z += v0.z + v1.z + v2.z + v3.z;
                sums[r].w += v0.w + v1.w + v2.w + v3.w;
            }
        }
    }
    for (; e < e1; e++) {
        const int s0 = srcs[e];
        const float4* r0 = (const float4*)(t + (long)s0 * ldc);
#pragma unroll
        for (int r = 0; r < NR; r++) {
            const int q = lane + r * 32;
            if (q < nq) {
                float4 v0 = r0[q];
                sums[r].x += v0.x;
                sums[r].y += v0.y;
                sums[r].z += v0.z;
                sums[r].w += v0.w;
            }
        }
    }

    const float di = dinv[i];
    float* orow = out + (long)i * F;
#pragma unroll
    for (int r = 0; r < NR; r++) {
        const int q = lane + r * 32;
        if (q < nq) {
            const int f = q * 4;
            const float s4[4] = { sums[r].x, sums[r].y, sums[r].z, sums[r].w };
#pragma unroll
            for (int c = 0; c < 4; c++) {
                const int ff = f + c;
                if (ff < F) orow[ff] = fmaf(di, s4[c], bias[ff]);
            }
        }
    }
}

// ---------------------------------------------------------------------------
// host
// ---------------------------------------------------------------------------
static void launch_gather(const float* t, const int* rowptr, const int* srcs,
                          const float* dinv, const float* bias, float* out,
                          int n, int F, int ldc) {
    const int blocks = (n + 7) / 8;
    const int nq = ldc / 4;
    if (nq > 32)
        gather4_kernel<2><<<blocks, 256>>>(t, rowptr, srcs, dinv, bias, out, n, F, ldc);
    else
        gather4_kernel<1><<<blocks, 256>>>(t, rowptr, srcs, dinv, bias, out, n, F, ldc);
}

extern "C" void kernel_launch(void* const* d_in, const int* in_sizes, int n_in,
                              void* d_out, int out_size) {
    const float* x   = (const float*)d_in[0];
    const int* eidx  = (const int*)d_in[1];
    const int E      = in_sizes[1] / 2;
    const int* srcp  = eidx;
    const int* dstp  = eidx + E;

    const float* W[5] = { (const float*)d_in[2], (const float*)d_in[4],
                          (const float*)d_in[6], (const float*)d_in[8],
                          (const float*)d_in[10] };
    const float* B[5] = { (const float*)d_in[3], (const float*)d_in[5],
                          (const float*)d_in[7], (const float*)d_in[9],
                          (const float*)d_in[11] };
    const int dims[6] = {512, 200, 175, 125, 75, 50};
    const int N = N_NODES;

    float *tmp, *bufA, *bufB, *dinv;
    int *deg, *rowptr, *cursor, *srcs, *bsums;
    cudaGetSymbolAddress((void**)&tmp,    g_tmp);
    cudaGetSymbolAddress((void**)&bufA,   g_bufA);
    cudaGetSymbolAddress((void**)&bufB,   g_bufB);
    cudaGetSymbolAddress((void**)&dinv,   g_dinv);
    cudaGetSymbolAddress((void**)&deg,    g_deg);
    cudaGetSymbolAddress((void**)&rowptr, g_rowptr);
    cudaGetSymbolAddress((void**)&cursor, g_cursor);
    cudaGetSymbolAddress((void**)&srcs,   g_srcs);
    cudaGetSymbolAddress((void**)&bsums,  g_bsums);

    const int nb = (N + 255) / 256;  // 391
    deg_zero_kernel<<<(N + 255) / 256, 256>>>(deg, N);
    deg_count_kernel<<<(E + 255) / 256, 256>>>(dstp, deg, E);
    dinv_kernel<<<(N + 255) / 256, 256>>>(deg, dinv, N);
    blocksum_kernel<<<nb, 256>>>(deg, bsums, N);
    scan_bsums_kernel<<<1, 512>>>(bsums, nb, rowptr, N);
    local_scan_kernel<<<nb, 256>>>(deg, bsums, rowptr, cursor, N);
    fill_kernel<<<(E + 255) / 256, 256>>>(srcp, dstp, cursor, srcs, E);

    const float* in_act = x;
    float* outs[5] = { bufA, bufB, bufA, bufB, (float*)d_out };

    for (int L = 0; L < 5; L++) {
        const int Fin = dims[L], Fout = dims[L + 1];
        const int ldc = (Fout + 3) & ~3;   // padded stride, %4 == 0
        dim3 ggrid((ldc + 63) / 64, (N + 127) / 128);
        if (L == 0)
            gemm_bf16x2_kernel<0><<<ggrid, 256>>>(in_act, W[L], dinv, tmp, N, Fin, Fout, ldc);
        else
            gemm_bf16x2_kernel<1><<<ggrid, 256>>>(in_act, W[L], dinv, tmp, N, Fin, Fout, ldc);

        launch_gather(tmp, rowptr, srcs, dinv, B[L], outs[L], N, Fout, ldc);
        in_act = outs[L];
    }
}